// round 1
// baseline (speedup 1.0000x reference)
#include <cuda_runtime.h>
#include <math.h>

#define BATCH   2
#define SEQ     2048
#define CMODEL  512
#define NHEADS  8
#define DK      64
#define DFF     2048
#define QKVC    1536
#define NTOK    (BATCH*SEQ)     /* 4096 */
#define NTOP    512
#define SCALE   0.125f
#define LNEPS   1e-5f
#define NEGINF  -3.402823466e38f

// ---------------- scratch (static device globals; no allocation) ----------------
__device__ float g_qkv[NTOK*QKVC];          // qkv activations; later reused as packed conv input
__device__ float g_hff[NTOK*DFF];           // FFN hidden
__device__ float g_attnO[NTOK*CMODEL];      // attention output (pre-projection)
__device__ float g_t1[NTOK*CMODEL];         // generic [NTOK,C] temp
__device__ float g_x1[NTOK*CMODEL];         // after LN1
__device__ float g_x2[NTOK*CMODEL];         // after LN2
__device__ float g_cy[NTOK*CMODEL];         // conv output (pre-pool)
__device__ float g_wr[3*CMODEL*CMODEL];     // repacked conv weight [3*C, C]
__device__ float g_rowmax[BATCH*NHEADS*SEQ];
__device__ float g_M[BATCH*NHEADS*SEQ];
__device__ float g_ksum[BATCH*NHEADS*DK];
__device__ float g_vmean[BATCH*NHEADS*DK];
__device__ int   g_topidx[BATCH*NHEADS*NTOP];

// ---------------- generic tiled SGEMM: C[M,N] = A[M,K] @ B[K,N] + bias, opt GELU ----------------
__global__ __launch_bounds__(256) void k_sgemm(
    const float* __restrict__ A, const float* __restrict__ B,
    const float* __restrict__ bias, float* __restrict__ C,
    int M, int N, int K, int gelu)
{
    __shared__ float As[8][128];
    __shared__ float Bs[8][128];
    const int bm = blockIdx.y * 128;
    const int bn = blockIdx.x * 128;
    const int t  = threadIdx.x;
    const int tx = t & 15, ty = t >> 4;

    float acc[8][8];
#pragma unroll
    for (int i = 0; i < 8; i++)
#pragma unroll
        for (int j = 0; j < 8; j++) acc[i][j] = 0.0f;

    const int arow = t >> 1, acol = (t & 1) * 4;
    const int brow = t >> 5, bcol = (t & 31) * 4;
    const float* Ap = A + (size_t)(bm + arow) * K + acol;
    const float* Bp = B + (size_t)brow * N + bn + bcol;

    for (int k0 = 0; k0 < K; k0 += 8) {
        float4 av = *(const float4*)(Ap + k0);
        float4 bv = *(const float4*)(Bp + (size_t)k0 * N);
        As[acol + 0][arow] = av.x; As[acol + 1][arow] = av.y;
        As[acol + 2][arow] = av.z; As[acol + 3][arow] = av.w;
        *(float4*)&Bs[brow][bcol] = bv;
        __syncthreads();
#pragma unroll
        for (int kk = 0; kk < 8; kk++) {
            float a[8], b[8];
            *(float4*)(a)     = *(float4*)&As[kk][ty * 8];
            *(float4*)(a + 4) = *(float4*)&As[kk][ty * 8 + 4];
            *(float4*)(b)     = *(float4*)&Bs[kk][tx * 8];
            *(float4*)(b + 4) = *(float4*)&Bs[kk][tx * 8 + 4];
#pragma unroll
            for (int i = 0; i < 8; i++)
#pragma unroll
                for (int j = 0; j < 8; j++) acc[i][j] += a[i] * b[j];
        }
        __syncthreads();
    }

#pragma unroll
    for (int i = 0; i < 8; i++) {
        const int row = bm + ty * 8 + i;
#pragma unroll
        for (int j = 0; j < 8; j++) {
            float v = acc[i][j] + bias[bn + tx * 8 + j];
            if (gelu) v = 0.5f * v * (1.0f + erff(v * 0.70710678118654752f));
            C[(size_t)row * N + bn + tx * 8 + j] = v;
        }
    }
}

// ---------------- per-(b,h) ksum / vmean ----------------
__global__ __launch_bounds__(256) void k_kstats()
{
    const int bh = blockIdx.x, b = bh >> 3, h = bh & 7;
    const int t = threadIdx.x;
    const int d = t & 63, c = t >> 6;    // 4 chunks of 512 rows
    float ks = 0.f, vs = 0.f;
    for (int n = c * 512; n < (c + 1) * 512; n++) {
        const float* p = g_qkv + (size_t)(b * SEQ + n) * QKVC + CMODEL + h * DK + d;
        ks += p[0];
        vs += p[CMODEL];
    }
    __shared__ float sk[256], sv[256];
    sk[t] = ks; sv[t] = vs;
    __syncthreads();
    if (t < 64) {
        float a = sk[t] + sk[t + 64] + sk[t + 128] + sk[t + 192];
        float v = sv[t] + sv[t + 64] + sv[t + 128] + sv[t + 192];
        g_ksum[bh * DK + t]  = a;
        g_vmean[bh * DK + t] = v * (1.0f / SEQ);
    }
}

// ---------------- streamed QK^T row-max + M (no score storage) ----------------
__global__ __launch_bounds__(256) void k_rowmax()
{
    const int bh = blockIdx.y, b = bh >> 3, h = bh & 7;
    const int bm = blockIdx.x * 128;
    const int t = threadIdx.x;
    const int tx = t & 15, ty = t >> 4;

    __shared__ float As[8][128];          // Q^T chunk
    __shared__ float Bs[8][128];          // K^T chunk
    __shared__ float red[128][16];
    __shared__ float ks[64];
    if (t < 64) ks[t] = g_ksum[bh * DK + t];

    float lmax[8];
#pragma unroll
    for (int i = 0; i < 8; i++) lmax[i] = NEGINF;

    const int arow = t >> 1, acol = (t & 1) * 4;
    const float* qbase = g_qkv + (size_t)(b * SEQ) * QKVC + h * DK;
    const float* kbase = qbase + CMODEL;

    for (int m0 = 0; m0 < SEQ; m0 += 128) {
        float acc[8][8];
#pragma unroll
        for (int i = 0; i < 8; i++)
#pragma unroll
            for (int j = 0; j < 8; j++) acc[i][j] = 0.0f;

        for (int k0 = 0; k0 < DK; k0 += 8) {
            float4 av = *(const float4*)(qbase + (size_t)(bm + arow) * QKVC + k0 + acol);
            float4 bv = *(const float4*)(kbase + (size_t)(m0 + arow) * QKVC + k0 + acol);
            As[acol + 0][arow] = av.x; As[acol + 1][arow] = av.y;
            As[acol + 2][arow] = av.z; As[acol + 3][arow] = av.w;
            Bs[acol + 0][arow] = bv.x; Bs[acol + 1][arow] = bv.y;
            Bs[acol + 2][arow] = bv.z; Bs[acol + 3][arow] = bv.w;
            __syncthreads();
#pragma unroll
            for (int kk = 0; kk < 8; kk++) {
                float a[8], bb[8];
                *(float4*)(a)      = *(float4*)&As[kk][ty * 8];
                *(float4*)(a + 4)  = *(float4*)&As[kk][ty * 8 + 4];
                *(float4*)(bb)     = *(float4*)&Bs[kk][tx * 8];
                *(float4*)(bb + 4) = *(float4*)&Bs[kk][tx * 8 + 4];
#pragma unroll
                for (int i = 0; i < 8; i++)
#pragma unroll
                    for (int j = 0; j < 8; j++) acc[i][j] += a[i] * bb[j];
            }
            __syncthreads();
        }
#pragma unroll
        for (int i = 0; i < 8; i++) {
            float mx = acc[i][0];
#pragma unroll
            for (int j = 1; j < 8; j++) mx = fmaxf(mx, acc[i][j]);
            lmax[i] = fmaxf(lmax[i], mx);
        }
    }

#pragma unroll
    for (int i = 0; i < 8; i++) red[ty * 8 + i][tx] = lmax[i];
    __syncthreads();
    if (t < 128) {
        float mx = red[t][0];
#pragma unroll
        for (int j = 1; j < 16; j++) mx = fmaxf(mx, red[t][j]);
        float qd = 0.f;
        const float* qp = qbase + (size_t)(bm + t) * QKVC;
#pragma unroll 8
        for (int d = 0; d < 64; d++) qd += qp[d] * ks[d];
        g_rowmax[bh * SEQ + bm + t] = SCALE * mx;
        g_M[bh * SEQ + bm + t]      = SCALE * mx - SCALE * qd * (1.0f / SEQ);
    }
}

// ---------------- exact top-512 per (b,h): in-smem bitonic sort (jax tie-break) ----------------
__global__ __launch_bounds__(1024) void k_topk()
{
    const int bh = blockIdx.x;
    const int t = threadIdx.x;
    __shared__ float sv[2048];
    __shared__ int   si[2048];
    sv[t]        = g_M[bh * SEQ + t];        si[t]        = t;
    sv[t + 1024] = g_M[bh * SEQ + t + 1024]; si[t + 1024] = t + 1024;

    for (int k = 2; k <= 2048; k <<= 1) {
        for (int j = k >> 1; j > 0; j >>= 1) {
            __syncthreads();
#pragma unroll 1
            for (int e = t; e < 2048; e += 1024) {
                const int p = e ^ j;
                if (p > e) {
                    float va = sv[e], vb = sv[p];
                    int   ia = si[e], ib = si[p];
                    // "gtr": a must precede b in final descending order (ties: lower idx first)
                    bool gtr = (va > vb) || (va == vb && ia < ib);
                    bool desc = ((e & k) == 0);
                    if (desc ? !gtr : gtr) {
                        sv[e] = vb; sv[p] = va;
                        si[e] = ib; si[p] = ia;
                    }
                }
            }
        }
    }
    __syncthreads();
    if (t < NTOP) g_topidx[bh * NTOP + t] = si[t];
}

// ---------------- fill all rows with vmean (unselected rows keep this) ----------------
__global__ __launch_bounds__(256) void k_fill()
{
    const int i = blockIdx.x * 256 + threadIdx.x;
    const int c = i & 511;
    const int tok = i >> 9;
    const int b = tok >> 11;
    g_attnO[i] = g_vmean[(b * NHEADS + (c >> 6)) * DK + (c & 63)];
}

// ---------------- softmax @ V for selected rows (row max known -> single pass) ----------------
__global__ __launch_bounds__(128) void k_attn_sel()
{
    const int bh = blockIdx.y, b = bh >> 3, h = bh & 7;
    const int t = threadIdx.x;

    __shared__ float Qs[16][65];
    __shared__ float Ks[64][65];
    __shared__ float Vs[64][65];
    __shared__ float Se[16][64];
    __shared__ float sume[16];
    __shared__ float rmax[16];
    __shared__ int   nidx[16];

    if (t < 16) {
        int n = g_topidx[bh * NTOP + blockIdx.x * 16 + t];
        nidx[t] = n;
        sume[t] = 0.f;
        rmax[t] = g_rowmax[bh * SEQ + n];
    }
    __syncthreads();

    const int r  = t >> 3;        // row owned (0..15)
    const int mg = (t & 7) * 8;   // score column group
    const int dg = (t & 7) * 8;   // output dim group

    {   // load Q rows (16 x 64)
        const int qr = t >> 3, c0 = (t & 7) * 8;
        const float* qp = g_qkv + (size_t)(b * SEQ + nidx[qr]) * QKVC + h * DK + c0;
        float4 q0 = *(const float4*)qp, q1 = *(const float4*)(qp + 4);
        Qs[qr][c0 + 0] = q0.x; Qs[qr][c0 + 1] = q0.y; Qs[qr][c0 + 2] = q0.z; Qs[qr][c0 + 3] = q0.w;
        Qs[qr][c0 + 4] = q1.x; Qs[qr][c0 + 5] = q1.y; Qs[qr][c0 + 6] = q1.z; Qs[qr][c0 + 7] = q1.w;
    }
    const float rm = rmax[r];

    float o[8];
#pragma unroll
    for (int i = 0; i < 8; i++) o[i] = 0.f;

    for (int m0 = 0; m0 < SEQ; m0 += 64) {
        __syncthreads();   // previous tile's Se/Vs consumers done
        for (int f = t; f < 1024; f += 128) {
            const int mr = f >> 4, c4 = (f & 15) * 4;
            const float* kp = g_qkv + (size_t)(b * SEQ + m0 + mr) * QKVC + CMODEL + h * DK + c4;
            float4 kv = *(const float4*)kp;
            float4 vv = *(const float4*)(kp + CMODEL);
            Ks[mr][c4 + 0] = kv.x; Ks[mr][c4 + 1] = kv.y; Ks[mr][c4 + 2] = kv.z; Ks[mr][c4 + 3] = kv.w;
            Vs[mr][c4 + 0] = vv.x; Vs[mr][c4 + 1] = vv.y; Vs[mr][c4 + 2] = vv.z; Vs[mr][c4 + 3] = vv.w;
        }
        __syncthreads();

        float s[8];
#pragma unroll
        for (int jj = 0; jj < 8; jj++) s[jj] = 0.f;
#pragma unroll 8
        for (int d = 0; d < 64; d++) {
            const float qv = Qs[r][d];
#pragma unroll
            for (int jj = 0; jj < 8; jj++) s[jj] += qv * Ks[mg + jj][d];
        }
        float lsum = 0.f;
#pragma unroll
        for (int jj = 0; jj < 8; jj++) {
            float ev = expf(s[jj] * SCALE - rm);
            Se[r][mg + jj] = ev;
            lsum += ev;
        }
        atomicAdd(&sume[r], lsum);
        __syncthreads();

#pragma unroll 8
        for (int m = 0; m < 64; m++) {
            const float ev = Se[r][m];
#pragma unroll
            for (int i = 0; i < 8; i++) o[i] += ev * Vs[m][dg + i];
        }
    }
    __syncthreads();
    const float inv = 1.0f / sume[r];
    float* op = g_attnO + (size_t)(b * SEQ + nidx[r]) * CMODEL + h * DK + dg;
#pragma unroll
    for (int i = 0; i < 8; i++) op[i] = o[i] * inv;
}

// ---------------- fused residual add + LayerNorm over C=512 ----------------
__global__ __launch_bounds__(128) void k_addln(
    const float* __restrict__ A, const float* __restrict__ Bv,
    const float* __restrict__ g, const float* __restrict__ be, float* __restrict__ O)
{
    const int row = blockIdx.x, t = threadIdx.x;
    float4 a = ((const float4*)(A  + (size_t)row * CMODEL))[t];
    float4 b = ((const float4*)(Bv + (size_t)row * CMODEL))[t];
    float v0 = a.x + b.x, v1 = a.y + b.y, v2 = a.z + b.z, v3 = a.w + b.w;

    __shared__ float ws[4];
    float s = v0 + v1 + v2 + v3;
#pragma unroll
    for (int o = 16; o > 0; o >>= 1) s += __shfl_xor_sync(0xffffffffu, s, o);
    if ((t & 31) == 0) ws[t >> 5] = s;
    __syncthreads();
    const float mean = (ws[0] + ws[1] + ws[2] + ws[3]) * (1.0f / CMODEL);
    v0 -= mean; v1 -= mean; v2 -= mean; v3 -= mean;
    float q = v0 * v0 + v1 * v1 + v2 * v2 + v3 * v3;
#pragma unroll
    for (int o = 16; o > 0; o >>= 1) q += __shfl_xor_sync(0xffffffffu, q, o);
    __syncthreads();
    if ((t & 31) == 0) ws[t >> 5] = q;
    __syncthreads();
    const float var = (ws[0] + ws[1] + ws[2] + ws[3]) * (1.0f / CMODEL);
    const float rs = rsqrtf(var + LNEPS);
    float4 gg = ((const float4*)g)[t], bb = ((const float4*)be)[t];
    float4 out;
    out.x = v0 * rs * gg.x + bb.x;
    out.y = v1 * rs * gg.y + bb.y;
    out.z = v2 * rs * gg.z + bb.z;
    out.w = v3 * rs * gg.w + bb.w;
    ((float4*)(O + (size_t)row * CMODEL))[t] = out;
}

// ---------------- conv weight repack: wr[k*C+ci, co] = conv_w[co, ci, k] ----------------
__global__ __launch_bounds__(256) void k_packW(const float* __restrict__ conv_w)
{
    const int i = blockIdx.x * 256 + threadIdx.x;
    const int co = i & 511;
    const int rr = i >> 9;
    const int ci = rr & 511;
    const int k  = rr >> 9;
    g_wr[i] = conv_w[(co * CMODEL + ci) * 3 + k];
}

// ---------------- gather circular-shifted x2 into packed conv input (reuses g_qkv) ----------------
__global__ __launch_bounds__(256) void k_packX()
{
    const int i = blockIdx.x * 256 + threadIdx.x;
    const int col = i % QKVC;
    const int tok = i / QKVC;
    const int b = tok >> 11, n = tok & 2047;
    const int k = col >> 9, ci = col & 511;
    const int ns = (n - 1 + k + SEQ) & (SEQ - 1);    // circular
    g_qkv[i] = g_x2[(size_t)(b * SEQ + ns) * CMODEL + ci];
}

// ---------------- maxpool(k3,s2,p1) + ELU + LayerNorm -> final output ----------------
__global__ __launch_bounds__(128) void k_poolln(
    const float* __restrict__ Y, const float* __restrict__ g,
    const float* __restrict__ be, float* __restrict__ O)
{
    const int row = blockIdx.x;           // b*1024 + j
    const int b = row >> 10, j = row & 1023;
    const int t = threadIdx.x;
    const int c = t * 4;

    float m0 = NEGINF, m1 = NEGINF, m2 = NEGINF, m3 = NEGINF;
#pragma unroll
    for (int dn = 0; dn < 3; dn++) {
        const int n = 2 * j - 1 + dn;
        if (n >= 0 && n < SEQ) {
            float4 w = *(const float4*)(Y + (size_t)(b * SEQ + n) * CMODEL + c);
            m0 = fmaxf(m0, w.x); m1 = fmaxf(m1, w.y);
            m2 = fmaxf(m2, w.z); m3 = fmaxf(m3, w.w);
        }
    }
    float v0 = m0 > 0.f ? m0 : expm1f(m0);
    float v1 = m1 > 0.f ? m1 : expm1f(m1);
    float v2 = m2 > 0.f ? m2 : expm1f(m2);
    float v3 = m3 > 0.f ? m3 : expm1f(m3);

    __shared__ float ws[4];
    float s = v0 + v1 + v2 + v3;
#pragma unroll
    for (int o = 16; o > 0; o >>= 1) s += __shfl_xor_sync(0xffffffffu, s, o);
    if ((t & 31) == 0) ws[t >> 5] = s;
    __syncthreads();
    const float mean = (ws[0] + ws[1] + ws[2] + ws[3]) * (1.0f / CMODEL);
    v0 -= mean; v1 -= mean; v2 -= mean; v3 -= mean;
    float q = v0 * v0 + v1 * v1 + v2 * v2 + v3 * v3;
#pragma unroll
    for (int o = 16; o > 0; o >>= 1) q += __shfl_xor_sync(0xffffffffu, q, o);
    __syncthreads();
    if ((t & 31) == 0) ws[t >> 5] = q;
    __syncthreads();
    const float var = (ws[0] + ws[1] + ws[2] + ws[3]) * (1.0f / CMODEL);
    const float rs = rsqrtf(var + LNEPS);
    float4 gg = ((const float4*)g)[t], bb = ((const float4*)be)[t];
    float4 out;
    out.x = v0 * rs * gg.x + bb.x;
    out.y = v1 * rs * gg.y + bb.y;
    out.z = v2 * rs * gg.z + bb.z;
    out.w = v3 * rs * gg.w + bb.w;
    ((float4*)(O + (size_t)row * CMODEL))[t] = out;
}

// ---------------- host orchestration ----------------
extern "C" void kernel_launch(void* const* d_in, const int* in_sizes, int n_in,
                              void* d_out, int out_size)
{
    (void)in_sizes; (void)n_in; (void)out_size;
    const float* x      = (const float*)d_in[0];
    const float* qkv_w  = (const float*)d_in[1];
    const float* qkv_b  = (const float*)d_in[2];
    const float* out_w  = (const float*)d_in[3];
    const float* out_b  = (const float*)d_in[4];
    const float* ffn_w1 = (const float*)d_in[5];
    const float* ffn_b1 = (const float*)d_in[6];
    const float* ffn_w2 = (const float*)d_in[7];
    const float* ffn_b2 = (const float*)d_in[8];
    const float* n1_g   = (const float*)d_in[9];
    const float* n1_b   = (const float*)d_in[10];
    const float* n2_g   = (const float*)d_in[11];
    const float* n2_b   = (const float*)d_in[12];
    const float* conv_w = (const float*)d_in[13];
    const float* conv_b = (const float*)d_in[14];
    const float* cn_g   = (const float*)d_in[15];
    const float* cn_b   = (const float*)d_in[16];
    float* out = (float*)d_out;

    float *p_qkv, *p_hff, *p_attnO, *p_t1, *p_x1, *p_x2, *p_cy, *p_wr;
    cudaGetSymbolAddress((void**)&p_qkv,   g_qkv);
    cudaGetSymbolAddress((void**)&p_hff,   g_hff);
    cudaGetSymbolAddress((void**)&p_attnO, g_attnO);
    cudaGetSymbolAddress((void**)&p_t1,    g_t1);
    cudaGetSymbolAddress((void**)&p_x1,    g_x1);
    cudaGetSymbolAddress((void**)&p_x2,    g_x2);
    cudaGetSymbolAddress((void**)&p_cy,    g_cy);
    cudaGetSymbolAddress((void**)&p_wr,    g_wr);

    // 1) QKV projection
    k_sgemm<<<dim3(QKVC / 128, NTOK / 128), 256>>>(x, qkv_w, qkv_b, p_qkv, NTOK, QKVC, CMODEL, 0);
    // 2) per-head key-sum / value-mean
    k_kstats<<<BATCH * NHEADS, 256>>>();
    // 3) streamed row-max of QK^T and sparsity measure M
    k_rowmax<<<dim3(SEQ / 128, BATCH * NHEADS), 256>>>();
    // 4) exact top-512 per head
    k_topk<<<BATCH * NHEADS, 1024>>>();
    // 5) default all rows to vmean (uniform-softmax result), then overwrite selected
    k_fill<<<(NTOK * CMODEL) / 256, 256>>>();
    k_attn_sel<<<dim3(NTOP / 16, BATCH * NHEADS), 128>>>();
    // 6) output projection + LN1
    k_sgemm<<<dim3(CMODEL / 128, NTOK / 128), 256>>>(p_attnO, out_w, out_b, p_t1, NTOK, CMODEL, CMODEL, 0);
    k_addln<<<NTOK, 128>>>(x, p_t1, n1_g, n1_b, p_x1);
    // 7) FFN + LN2
    k_sgemm<<<dim3(DFF / 128, NTOK / 128), 256>>>(p_x1, ffn_w1, ffn_b1, p_hff, NTOK, DFF, CMODEL, 1);
    k_sgemm<<<dim3(CMODEL / 128, NTOK / 128), 256>>>(p_hff, ffn_w2, ffn_b2, p_t1, NTOK, CMODEL, DFF, 0);
    k_addln<<<NTOK, 128>>>(p_x1, p_t1, n2_g, n2_b, p_x2);
    // 8) circular conv1d(k=3) as GEMM over packed input
    k_packW<<<(3 * CMODEL * CMODEL) / 256, 256>>>(conv_w);
    k_packX<<<(NTOK * QKVC) / 256, 256>>>();
    k_sgemm<<<dim3(CMODEL / 128, NTOK / 128), 256>>>(p_qkv, p_wr, conv_b, p_cy, NTOK, CMODEL, 3 * CMODEL, 0);
    // 9) maxpool + ELU + LN -> d_out
    k_poolln<<<BATCH * (SEQ / 2), 128>>>(p_cy, cn_g, cn_b, out);
}